// round 9
// baseline (speedup 1.0000x reference)
#include <cuda_runtime.h>
#include <cuda_bf16.h>
#include <cstdint>

#define BB 2
#define SS 2048
#define EE 512
#define HH 8
#define DD 64
#define NKV ((size_t)BB * SS * HH * DD)   // 2097152

typedef unsigned long long ull;

// ---------------- bf16 helpers ----------------
// pack {lo,hi} floats -> bf16x2 word (lo in low 16 bits)
__device__ __forceinline__ uint32_t cvt2(float lo, float hi) {
    uint32_t r; asm("cvt.rn.bf16x2.f32 %0, %1, %2;" : "=r"(r) : "f"(hi), "f"(lo)); return r;
}
__device__ __forceinline__ float lof(uint32_t w) { return __uint_as_float(w << 16); }
__device__ __forceinline__ float hif(uint32_t w) { return __uint_as_float(w & 0xffff0000u); }

__device__ __forceinline__ uint32_t smem_to_u32(const void* p) {
    uint32_t a; asm("{ .reg .u64 t; cvta.to.shared.u64 t, %1; cvt.u32.u64 %0, t; }" : "=r"(a) : "l"(p)); return a;
}

// ---------------- mma.sync + ldmatrix (baseline PTX, OK on compute_103) ----
__device__ __forceinline__ void mma_bf16(float* c, const uint32_t* a, uint32_t b0, uint32_t b1) {
    asm volatile("mma.sync.aligned.m16n8k16.row.col.f32.bf16.bf16.f32 "
        "{%0,%1,%2,%3}, {%4,%5,%6,%7}, {%8,%9}, {%0,%1,%2,%3};"
        : "+f"(c[0]), "+f"(c[1]), "+f"(c[2]), "+f"(c[3])
        : "r"(a[0]), "r"(a[1]), "r"(a[2]), "r"(a[3]), "r"(b0), "r"(b1));
}
__device__ __forceinline__ void ldsm_x4(uint32_t* r, uint32_t addr) {
    asm volatile("ldmatrix.sync.aligned.m8n8.x4.shared.b16 {%0,%1,%2,%3}, [%4];"
        : "=r"(r[0]), "=r"(r[1]), "=r"(r[2]), "=r"(r[3]) : "r"(addr));
}
__device__ __forceinline__ void ldsm_x4_t(uint32_t* r, uint32_t addr) {
    asm volatile("ldmatrix.sync.aligned.m8n8.x4.trans.shared.b16 {%0,%1,%2,%3}, [%4];"
        : "=r"(r[0]), "=r"(r[1]), "=r"(r[2]), "=r"(r[3]) : "r"(addr));
}

// ---------------- scratch ----------------
__device__ float g_Q[(size_t)BB * SS * EE];
__device__ float g_AO[(size_t)BB * SS * EE];
__device__ ull g_maskBits[(size_t)BB * SS * SS / 64];
__device__ int g_maskKind;
__device__ __nv_bfloat16 g_KVsp[4][NKV];   // planes: Kh, Kl, Vh, Vl

// ---------------- mask dtype detect + bitpack ----------------
__global__ void detect_mask_kernel(const unsigned int* __restrict__ w)
{
    int i32ok = 1, f32ok = 1;
    for (int i = threadIdx.x; i < 16384; i += 256) {
        unsigned int v = w[i];
        if (v > 1u) i32ok = 0;
        if (v != 0u && v != 0x3F800000u) f32ok = 0;
    }
    i32ok = __syncthreads_and(i32ok);
    f32ok = __syncthreads_and(f32ok);
    if (threadIdx.x == 0) g_maskKind = i32ok ? 1 : (f32ok ? 2 : 0);
}

__global__ __launch_bounds__(256)
void bitpack_mask_kernel(const void* __restrict__ mask)
{
    size_t u = (size_t)blockIdx.x * 256 + threadIdx.x;
    int kind = g_maskKind;
    ull bits = 0;
    if (kind == 1) {
        const int4* p = (const int4*)mask + u * 16;
        #pragma unroll
        for (int w = 0; w < 16; ++w) {
            int4 a = p[w];
            bits |= ((ull)(a.x != 0)) << (4 * w) | ((ull)(a.y != 0)) << (4 * w + 1) |
                    ((ull)(a.z != 0)) << (4 * w + 2) | ((ull)(a.w != 0)) << (4 * w + 3);
        }
    } else if (kind == 2) {
        const float4* p = (const float4*)mask + u * 16;
        #pragma unroll
        for (int w = 0; w < 16; ++w) {
            float4 a = p[w];
            bits |= ((ull)(a.x != 0.f)) << (4 * w) | ((ull)(a.y != 0.f)) << (4 * w + 1) |
                    ((ull)(a.z != 0.f)) << (4 * w + 2) | ((ull)(a.w != 0.f)) << (4 * w + 3);
        }
    } else {
        const ull* p = (const ull*)mask + u * 8;
        #pragma unroll
        for (int w = 0; w < 8; ++w) {
            ull v = p[w];
            #pragma unroll
            for (int b8 = 0; b8 < 8; ++b8)
                bits |= ((ull)(((v >> (8 * b8)) & 0xffull) != 0)) << (8 * w + b8);
        }
    }
    g_maskBits[u] = bits;
}

// ---------------- K/V bf16 hi/lo split precompute ----------------
__global__ __launch_bounds__(256)
void kvsplit_kernel(const float* __restrict__ K, const float* __restrict__ V)
{
    size_t i4 = (size_t)blockIdx.x * 256 + threadIdx.x;   // float4 index
    {
        float4 v = ((const float4*)K)[i4];
        uint32_t h0 = cvt2(v.x, v.y), h1 = cvt2(v.z, v.w);
        ((uint2*)g_KVsp[0])[i4] = make_uint2(h0, h1);
        ((uint2*)g_KVsp[1])[i4] = make_uint2(cvt2(v.x - lof(h0), v.y - hif(h0)),
                                             cvt2(v.z - lof(h1), v.w - hif(h1)));
    }
    {
        float4 v = ((const float4*)V)[i4];
        uint32_t h0 = cvt2(v.x, v.y), h1 = cvt2(v.z, v.w);
        ((uint2*)g_KVsp[2])[i4] = make_uint2(h0, h1);
        ((uint2*)g_KVsp[3])[i4] = make_uint2(cvt2(v.x - lof(h0), v.y - hif(h0)),
                                             cvt2(v.z - lof(h1), v.w - hif(h1)));
    }
}

// ---------------- HMMA GEMM: C[M x 512] = A[M x 512] * B[512 x 512] --------
#define GLA 40
#define GLB 72

__global__ __launch_bounds__(128, 2)
void gemm_mma_kernel(const float* __restrict__ A, const float* __restrict__ Bm,
                     float* __restrict__ C)
{
    __shared__ __align__(16) __nv_bfloat16 sAh[128 * GLA], sAl[128 * GLA];
    __shared__ __align__(16) __nv_bfloat16 sBh[32 * GLB], sBl[32 * GLB];

    const int tid = threadIdx.x;
    const int warp = tid >> 5, lane = tid & 31;
    const int g = lane >> 3, lrow = lane & 7;
    const int mbase = blockIdx.x * 128, nbase = blockIdx.y * 64;

    float Ca[2][8][4];
    #pragma unroll
    for (int i = 0; i < 2; ++i)
        #pragma unroll
        for (int j = 0; j < 8; ++j)
            #pragma unroll
            for (int r = 0; r < 4; ++r) Ca[i][j][r] = 0.f;

    const int arow = warp * 32 + (g & 1) * 8 + lrow;
    const int acol = (g >> 1) * 8;
    const uint32_t bOff = (uint32_t)(((g & 1) * 8 + lrow) * GLB + (g >> 1) * 8) * 2;
    const uint32_t uBh = smem_to_u32(sBh), uBl = smem_to_u32(sBl);

    #pragma unroll 1
    for (int kk = 0; kk < 512; kk += 32) {
        __syncthreads();
        {
            const float4* ar = (const float4*)(A + (size_t)(mbase + tid) * 512 + kk);
            uint32_t* ah = (uint32_t*)(sAh + tid * GLA);
            uint32_t* al = (uint32_t*)(sAl + tid * GLA);
            #pragma unroll
            for (int i = 0; i < 8; ++i) {
                float4 v = ar[i];
                uint32_t h0 = cvt2(v.x, v.y), h1 = cvt2(v.z, v.w);
                ah[2 * i] = h0; ah[2 * i + 1] = h1;
                al[2 * i] = cvt2(v.x - lof(h0), v.y - hif(h0));
                al[2 * i + 1] = cvt2(v.z - lof(h1), v.w - hif(h1));
            }
        }
        {
            int br = tid >> 2, bc = (tid & 3) * 16;
            const float4* bp = (const float4*)(Bm + (size_t)(kk + br) * 512 + nbase + bc);
            uint32_t* bh = (uint32_t*)(sBh + br * GLB + bc);
            uint32_t* bl = (uint32_t*)(sBl + br * GLB + bc);
            #pragma unroll
            for (int i = 0; i < 4; ++i) {
                float4 v = bp[i];
                uint32_t h0 = cvt2(v.x, v.y), h1 = cvt2(v.z, v.w);
                bh[2 * i] = h0; bh[2 * i + 1] = h1;
                bl[2 * i] = cvt2(v.x - lof(h0), v.y - hif(h0));
                bl[2 * i + 1] = cvt2(v.z - lof(h1), v.w - hif(h1));
            }
        }
        __syncthreads();

        uint32_t Ah[2][2][4], Al[2][2][4];
        #pragma unroll
        for (int i = 0; i < 2; ++i)
            #pragma unroll
            for (int kb = 0; kb < 2; ++kb) {
                ldsm_x4(Ah[i][kb], smem_to_u32(sAh + (arow + i * 16) * GLA + acol + kb * 16));
                ldsm_x4(Al[i][kb], smem_to_u32(sAl + (arow + i * 16) * GLA + acol + kb * 16));
            }

        #pragma unroll
        for (int np = 0; np < 4; ++np) {
            #pragma unroll
            for (int kb = 0; kb < 2; ++kb) {
                uint32_t Bh[4], Bl[4];
                uint32_t off = (uint32_t)(kb * 16 * GLB + np * 16) * 2;
                ldsm_x4_t(Bh, uBh + off + bOff);
                ldsm_x4_t(Bl, uBl + off + bOff);
                #pragma unroll
                for (int i = 0; i < 2; ++i) mma_bf16(Ca[i][2 * np], Ah[i][kb], Bh[0], Bh[1]);
                #pragma unroll
                for (int i = 0; i < 2; ++i) mma_bf16(Ca[i][2 * np + 1], Ah[i][kb], Bh[2], Bh[3]);
                #pragma unroll
                for (int i = 0; i < 2; ++i) mma_bf16(Ca[i][2 * np], Ah[i][kb], Bl[0], Bl[1]);
                #pragma unroll
                for (int i = 0; i < 2; ++i) mma_bf16(Ca[i][2 * np + 1], Ah[i][kb], Bl[2], Bl[3]);
                #pragma unroll
                for (int i = 0; i < 2; ++i) mma_bf16(Ca[i][2 * np], Al[i][kb], Bh[0], Bh[1]);
                #pragma unroll
                for (int i = 0; i < 2; ++i) mma_bf16(Ca[i][2 * np + 1], Al[i][kb], Bh[2], Bh[3]);
            }
        }
    }

    #pragma unroll
    for (int i = 0; i < 2; ++i) {
        int r0 = mbase + warp * 32 + i * 16 + (lane >> 2);
        float* c0 = C + (size_t)r0 * 512 + nbase;
        float* c1 = c0 + (size_t)8 * 512;
        #pragma unroll
        for (int nb = 0; nb < 8; ++nb) {
            int d = nb * 8 + (lane & 3) * 2;
            *(float2*)(c0 + d) = make_float2(Ca[i][nb][0], Ca[i][nb][1]);
            *(float2*)(c1 + d) = make_float2(Ca[i][nb][2], Ca[i][nb][3]);
        }
    }
}

// ---------------- HMMA flash attention (16 rows/warp, 64 rows/CTA) ---------
#define LST 72
#define TS (64 * LST)   // one tile plane in bf16 elems

__global__ __launch_bounds__(128, 4)
void attn_mma_kernel(const ull* __restrict__ mbits,
                     const float* __restrict__ Q, float* __restrict__ O)
{
    __shared__ __align__(16) __nv_bfloat16 sT[4 * TS];   // Kh | Kl | Vh | Vl

    const int b = blockIdx.z, h = blockIdx.y;
    const int qbase = blockIdx.x * 64;
    const int tid = threadIdx.x;
    const int warp = tid >> 5, lane = tid & 31;
    const int g = lane >> 3, lrow = lane & 7;

    // ---- stage Q (scaled 1/8, hi/lo) into tiles 0/1: 2 threads per row ----
    {
        int row = tid & 63, dh = (tid >> 6) * 32;
        const float4* qr = (const float4*)(Q + (size_t)(b * SS + qbase + row) * EE + h * DD + dh);
        uint32_t* ph = (uint32_t*)(sT + row * LST + dh);
        uint32_t* pl = (uint32_t*)(sT + TS + row * LST + dh);
        #pragma unroll
        for (int i = 0; i < 8; ++i) {
            float4 v = qr[i];
            v.x *= 0.125f; v.y *= 0.125f; v.z *= 0.125f; v.w *= 0.125f;
            uint32_t h0 = cvt2(v.x, v.y), h1 = cvt2(v.z, v.w);
            ph[2 * i] = h0; ph[2 * i + 1] = h1;
            pl[2 * i] = cvt2(v.x - lof(h0), v.y - hif(h0));
            pl[2 * i + 1] = cvt2(v.z - lof(h1), v.w - hif(h1));
        }
    }
    __syncthreads();

    // ---- persistent Q A-fragments ----
    uint32_t Qh[4][4], Ql[4][4];
    {
        int arow = warp * 16 + (g & 1) * 8 + lrow;
        int acol = (g >> 1) * 8;
        #pragma unroll
        for (int kb = 0; kb < 4; ++kb) {
            ldsm_x4(Qh[kb], smem_to_u32(sT + arow * LST + acol + kb * 16));
            ldsm_x4(Ql[kb], smem_to_u32(sT + TS + arow * LST + acol + kb * 16));
        }
    }

    float Oa[8][4];
    #pragma unroll
    for (int j = 0; j < 8; ++j)
        #pragma unroll
        for (int r = 0; r < 4; ++r) Oa[j][r] = 0.f;
    float lsum0 = 0.f, lsum1 = 0.f;

    const uint32_t uB = smem_to_u32(sT);
    const uint32_t uKh = uB, uKl = uB + TS * 2, uVh = uB + 2 * TS * 2, uVl = uB + 3 * TS * 2;
    const uint32_t kOff = (uint32_t)(((g >> 1) * 8 + lrow) * LST + (g & 1) * 8) * 2;
    const uint32_t vOff = (uint32_t)(((g & 1) * 8 + lrow) * LST + (g >> 1) * 8) * 2;
    const ull* mrow = mbits + (size_t)(b * SS + qbase + warp * 16) * (SS / 64);

    #pragma unroll 1
    for (int t = 0; t < SS / 64; ++t) {
        const int kt = t * 64;
        __syncthreads();
        // ---- stage K/V tiles: pure 16B copies from precomputed planes ----
        #pragma unroll
        for (int r2 = 0; r2 < 2; ++r2) {
            int idx = tid + 128 * r2;
            int tile = idx >> 6, row = idx & 63;
            const uint4* src = (const uint4*)(g_KVsp[tile] +
                ((size_t)(b * SS + kt + row) * HH + h) * DD);
            uint4* dst = (uint4*)(sT + tile * TS + row * LST);
            #pragma unroll
            for (int i = 0; i < 8; ++i) dst[i] = src[i];
        }
        __syncthreads();

        // ---- S = Q K^T (3-term split) ----
        float S[8][4];
        #pragma unroll
        for (int j = 0; j < 8; ++j)
            #pragma unroll
            for (int r = 0; r < 4; ++r) S[j][r] = 0.f;

        #pragma unroll
        for (int np = 0; np < 4; ++np) {
            #pragma unroll
            for (int kb = 0; kb < 4; ++kb) {
                uint32_t Bh[4], Bl[4];
                uint32_t off = (uint32_t)(np * 16 * LST + kb * 16) * 2;
                ldsm_x4(Bh, uKh + off + kOff);
                ldsm_x4(Bl, uKl + off + kOff);
                mma_bf16(S[2 * np], Qh[kb], Bh[0], Bh[1]);
                mma_bf16(S[2 * np + 1], Qh[kb], Bh[2], Bh[3]);
                mma_bf16(S[2 * np], Qh[kb], Bl[0], Bl[1]);
                mma_bf16(S[2 * np + 1], Qh[kb], Bl[2], Bl[3]);
                mma_bf16(S[2 * np], Ql[kb], Bh[0], Bh[1]);
                mma_bf16(S[2 * np + 1], Ql[kb], Bh[2], Bh[3]);
            }
        }

        // ---- softmax (masked -> 0) + pack P A-frags hi/lo ----
        uint32_t Ph[4][4], Pl[4][4];
        ull mw0 = mrow[(size_t)(lane >> 2) * (SS / 64) + t];
        ull mw1 = mrow[(size_t)(8 + (lane >> 2)) * (SS / 64) + t];
        #pragma unroll
        for (int nb = 0; nb < 8; ++nb) {
            int p0 = nb * 8 + (lane & 3) * 2;
            float e0 = ((mw0 >> p0) & 1ull) ? 0.f : __expf(S[nb][0]);
            float e1 = ((mw0 >> (p0 + 1)) & 1ull) ? 0.f : __expf(S[nb][1]);
            float e2 = ((mw1 >> p0) & 1ull) ? 0.f : __expf(S[nb][2]);
            float e3 = ((mw1 >> (p0 + 1)) & 1ull) ? 0.f : __expf(S[nb][3]);
            lsum0 += e0 + e1;
            lsum1 += e2 + e3;
            int kb = nb >> 1, sub = (nb & 1) * 2;
            uint32_t h01 = cvt2(e0, e1), h23 = cvt2(e2, e3);
            Ph[kb][sub] = h01;
            Ph[kb][sub + 1] = h23;
            Pl[kb][sub] = cvt2(e0 - lof(h01), e1 - hif(h01));
            Pl[kb][sub + 1] = cvt2(e2 - lof(h23), e3 - hif(h23));
        }

        // ---- O += P V (3-term split), V frags via ldmatrix.trans ----
        #pragma unroll
        for (int dp = 0; dp < 4; ++dp) {
            #pragma unroll
            for (int kb = 0; kb < 4; ++kb) {
                uint32_t Bh[4], Bl[4];
                uint32_t off = (uint32_t)(kb * 16 * LST + dp * 16) * 2;
                ldsm_x4_t(Bh, uVh + off + vOff);
                ldsm_x4_t(Bl, uVl + off + vOff);
                mma_bf16(Oa[2 * dp], Ph[kb], Bh[0], Bh[1]);
                mma_bf16(Oa[2 * dp + 1], Ph[kb], Bh[2], Bh[3]);
                mma_bf16(Oa[2 * dp], Ph[kb], Bl[0], Bl[1]);
                mma_bf16(Oa[2 * dp + 1], Ph[kb], Bl[2], Bl[3]);
                mma_bf16(Oa[2 * dp], Pl[kb], Bh[0], Bh[1]);
                mma_bf16(Oa[2 * dp + 1], Pl[kb], Bh[2], Bh[3]);
            }
        }
    }

    // ---- normalize + store ----
    lsum0 += __shfl_xor_sync(0xffffffffu, lsum0, 1);
    lsum0 += __shfl_xor_sync(0xffffffffu, lsum0, 2);
    lsum1 += __shfl_xor_sync(0xffffffffu, lsum1, 1);
    lsum1 += __shfl_xor_sync(0xffffffffu, lsum1, 2);
    float inv0 = 1.f / lsum0, inv1 = 1.f / lsum1;
    int r0 = qbase + warp * 16 + (lane >> 2);
    float* o0 = O + (size_t)(b * SS + r0) * EE + h * DD;
    float* o1 = o0 + (size_t)8 * EE;
    #pragma unroll
    for (int nb = 0; nb < 8; ++nb) {
        int d = nb * 8 + (lane & 3) * 2;
        *(float2*)(o0 + d) = make_float2(Oa[nb][0] * inv0, Oa[nb][1] * inv0);
        *(float2*)(o1 + d) = make_float2(Oa[nb][2] * inv1, Oa[nb][3] * inv1);
    }
}

// ---------------- launch ----------------
extern "C" void kernel_launch(void* const* d_in, const int* in_sizes, int n_in,
                              void* d_out, int out_size)
{
    const float* inputs = (const float*)d_in[0];
    const float* keys = (const float*)d_in[1];
    const float* values = (const float*)d_in[2];
    const float* wq = (const float*)d_in[3];
    const float* wo = (const float*)d_in[4];
    const void* mask_raw = d_in[5];
    float* out = (float*)d_out;

    float* qbuf; float* aobuf; ull* mbits;
    cudaGetSymbolAddress((void**)&qbuf, g_Q);
    cudaGetSymbolAddress((void**)&aobuf, g_AO);
    cudaGetSymbolAddress((void**)&mbits, g_maskBits);

    detect_mask_kernel<<<1, 256>>>((const unsigned int*)mask_raw);
    bitpack_mask_kernel<<<(BB * SS * SS / 64) / 256, 256>>>(mask_raw);
    kvsplit_kernel<<<(int)(NKV / 4 / 256), 256>>>(keys, values);

    dim3 ggrid(32, 8);
    gemm_mma_kernel<<<ggrid, 128>>>(inputs, wq, qbuf);
    attn_mma_kernel<<<dim3(SS / 64, HH, BB), 128>>>(mbits, qbuf, aobuf);
    gemm_mma_kernel<<<ggrid, 128>>>(aobuf, wo, out);
}